// round 6
// baseline (speedup 1.0000x reference)
#include <cuda_runtime.h>
#include <cuda_bf16.h>

// Problem dims
#define PB 2048
#define PT 512
#define PI 64
#define PH 128
#define PKW 192          // I + H
#define TB 16            // batch rows per CTA
#define NTHR 256

// SMEM layout (floats)
#define WROW 128                    // w row: 128 floats, no pad (broadcast loads -> no conflicts)
#define WBUF (PKW * WROW)           // 24576 per stage
#define W_OFF 0
#define XROW 32                     // duplicated row: 16 b * 2 copies
#define X_OFF (2 * WBUF)            // 49152
#define XBUF (PI * XROW)            // 2048
#define H_OFF (X_OFF + 2 * XBUF)    // 53248
#define HBUF (PH * XROW)            // 4096
#define B_OFF (H_OFF + HBUF)        // 57344
#define I_OFF (B_OFF + 2 * PH)      // 57600
#define SMEM_FLOATS (I_OFF + 32)    // 57632
#define SMEM_BYTES (SMEM_FLOATS * 4) // 230528 B  (fits 232448 max opt-in)

typedef unsigned long long ull;

// Pre-transposed weights: Wt[t][k][j], k in [0,192): k<64 -> W_xh, k>=64 -> W_hh
__device__ __align__(16) float g_Wt[(size_t)PT * PKW * PH];

// ---------------- helpers ----------------

__device__ __forceinline__ void cp_async16(void* smem_dst, const void* gsrc) {
    unsigned saddr = (unsigned)__cvta_generic_to_shared(smem_dst);
    asm volatile("cp.async.cg.shared.global [%0], [%1], 16;\n" :: "r"(saddr), "l"(gsrc) : "memory");
}
__device__ __forceinline__ void cp_commit() {
    asm volatile("cp.async.commit_group;\n" ::: "memory");
}
__device__ __forceinline__ void cp_wait_all() {
    asm volatile("cp.async.wait_group 0;\n" ::: "memory");
}

// packed fp32x2 FMA (Blackwell FFMA2)
__device__ __forceinline__ void ffma2(ull& d, ull a, ull b) {
    asm("fma.rn.f32x2 %0, %1, %2, %0;" : "+l"(d) : "l"(a), "l"(b));
}
__device__ __forceinline__ void unpack2(ull v, float& lo, float& hi) {
    asm("mov.b64 {%0, %1}, %2;" : "=f"(lo), "=f"(hi) : "l"(v));
}
// store duplicated pair {v, v} (8B)
__device__ __forceinline__ void st_dup2(float* p, float v) {
    unsigned saddr = (unsigned)__cvta_generic_to_shared(p);
    asm volatile("st.shared.v2.f32 [%0], {%1, %1};" :: "r"(saddr), "f"(v) : "memory");
}

__device__ __forceinline__ float fast_tanh(float v) {
    v = fminf(9.0f, fmaxf(-9.0f, v));
    float e = __expf(2.0f * v);
    return __fdividef(e - 1.0f, e + 1.0f);
}

// ---------------- pre-transpose kernels ----------------
// Wt[(t*192 + k)*128 + j] = (k<64) ? Wxh[(t*128+j)*64 + k] : Whh[(t*128+j)*128 + (k-64)]

__global__ void transpose_wxh(const float* __restrict__ Wxh) {
    __shared__ float tile[32][33];
    int t = blockIdx.z;
    int k0 = blockIdx.x * 32;
    int j0 = blockIdx.y * 32;
    for (int i = threadIdx.y; i < 32; i += 8)
        tile[i][threadIdx.x] = Wxh[((size_t)t * PH + (j0 + i)) * PI + k0 + threadIdx.x];
    __syncthreads();
    for (int i = threadIdx.y; i < 32; i += 8)
        g_Wt[((size_t)t * PKW + (k0 + i)) * PH + j0 + threadIdx.x] = tile[threadIdx.x][i];
}

__global__ void transpose_whh(const float* __restrict__ Whh) {
    __shared__ float tile[32][33];
    int t = blockIdx.z;
    int k0 = blockIdx.x * 32;
    int j0 = blockIdx.y * 32;
    for (int i = threadIdx.y; i < 32; i += 8)
        tile[i][threadIdx.x] = Whh[((size_t)t * PH + (j0 + i)) * PH + k0 + threadIdx.x];
    __syncthreads();
    for (int i = threadIdx.y; i < 32; i += 8)
        g_Wt[((size_t)t * PKW + (64 + k0 + i)) * PH + j0 + threadIdx.x] = tile[threadIdx.x][i];
}

// ---------------- main RNN kernel ----------------

__device__ __forceinline__ void load_w(int t, int buf, int tid,
                                       float* wS, float* bS,
                                       const float* __restrict__ bhh) {
    const float* src = g_Wt + (size_t)t * PKW * PH;
    float* dst = wS + buf * WBUF;
    // contiguous 96 KB: 6144 chunks of 16B, 24 per thread
#pragma unroll
    for (int i = 0; i < 24; i++) {
        int c = tid + i * NTHR;
        cp_async16(dst + c * 4, src + c * 4);
    }
    if (tid < 32)
        cp_async16(bS + buf * PH + tid * 4, bhh + (size_t)t * PH + tid * 4);
}

__global__ void __launch_bounds__(NTHR)
rnn_kernel(const float* __restrict__ x, const int* __restrict__ lens,
           const float* __restrict__ bhh, const float* __restrict__ Wout,
           const float* __restrict__ bout, float* __restrict__ out) {
    extern __shared__ float sm[];
    float* wS = sm + W_OFF;
    float* xD = sm + X_OFF;   // [2][64][32]  duplicated-transposed x
    float* hD = sm + H_OFF;   // [128][32]    duplicated-transposed h
    float* bS = sm + B_OFF;
    int* iS = (int*)(sm + I_OFF);

    const int tid  = threadIdx.x;
    const int wid  = tid >> 5;
    const int lane = tid & 31;
    const int jqo  = lane & 3;        // which of warp's 4 j-quads
    const int bp   = lane >> 2;       // batch-pair 0..7
    const int j0   = wid * 16 + jqo * 4;  // thread's 4 j outputs
    const int b0   = bp * 2;
    const int base = blockIdx.x * TB;

    if (tid < TB) iS[tid] = lens[base + tid];
    for (int i = tid; i < HBUF; i += NTHR) hD[i] = 0.0f;
    __syncthreads();
    if (tid == 0) {
        int m = 0;
#pragma unroll
        for (int i = 0; i < TB; i++) m = max(m, iS[i]);
        iS[TB] = m;
    }
    __syncthreads();

    const int tmax = iS[TB];
    const int len0 = iS[b0];
    const int len1 = iS[b0 + 1];

    // x staging mapping: thread -> (row sxb, k-quad sxk); tids 0..15 coalesce over k
    const int sxb = tid >> 4;
    const int sxk = (tid & 15) * 4;
    const float* xsrc = x + ((size_t)(base + sxb) * PT) * PI + sxk;

    if (tmax > 0) {
        float4 xr = *(const float4*)xsrc;   // t = 0
        {
            float* p = xD + sxk * XROW + 2 * sxb;
            st_dup2(p, xr.x); st_dup2(p + XROW, xr.y);
            st_dup2(p + 2 * XROW, xr.z); st_dup2(p + 3 * XROW, xr.w);
        }
        load_w(0, 0, tid, wS, bS, bhh);
        cp_commit();
    }

    for (int t = 0; t < tmax; t++) {
        const int buf = t & 1;
        cp_wait_all();
        __syncthreads();   // stage t visible; prior-iter readers of buf^1 done

        if (t + 1 < tmax) load_w(t + 1, buf ^ 1, tid, wS, bS, bhh);
        cp_commit();
        const bool havex = (t + 1 < tmax);
        float4 xn;
        if (havex) xn = *(const float4*)(xsrc + (size_t)(t + 1) * PI);

        const float* wb = wS + buf * WBUF + j0;
        const float* ab = xD + buf * XBUF + bp * 4;
        const float* bb = bS + buf * PH;

        // acc[pair p][batch i]; pairs: (j0,j0+1) and (j0+2,j0+3)
        ulonglong2 bv = *(const ulonglong2*)(bb + j0);
        ull a00 = bv.x, a01 = bv.x;   // pair 0, b0 / b0+1
        ull a10 = bv.y, a11 = bv.y;   // pair 1, b0 / b0+1

        // x phase: k in [0,64)
#pragma unroll 8
        for (int k = 0; k < PI; k++) {
            ulonglong2 wv = *(const ulonglong2*)(wb + k * WROW);
            ulonglong2 av = *(const ulonglong2*)(ab + k * XROW);
            ffma2(a00, wv.x, av.x);
            ffma2(a01, wv.x, av.y);
            ffma2(a10, wv.y, av.x);
            ffma2(a11, wv.y, av.y);
        }
        // h phase: k in [0,128)
        {
            const float* wh = wb + PI * WROW;
            const float* hb = hD + bp * 4;
#pragma unroll 8
            for (int k = 0; k < PH; k++) {
                ulonglong2 wv = *(const ulonglong2*)(wh + k * WROW);
                ulonglong2 av = *(const ulonglong2*)(hb + k * XROW);
                ffma2(a00, wv.x, av.x);
                ffma2(a01, wv.x, av.y);
                ffma2(a10, wv.y, av.x);
                ffma2(a11, wv.y, av.y);
            }
        }

        __syncthreads();   // all hD reads done before writes

        if (t < len0) {
            float f0, f1, f2, f3;
            unpack2(a00, f0, f1);
            unpack2(a10, f2, f3);
            float* p = hD + j0 * XROW + 2 * b0;
            st_dup2(p,            fast_tanh(f0));
            st_dup2(p + XROW,     fast_tanh(f1));
            st_dup2(p + 2 * XROW, fast_tanh(f2));
            st_dup2(p + 3 * XROW, fast_tanh(f3));
        }
        if (t < len1) {
            float f0, f1, f2, f3;
            unpack2(a01, f0, f1);
            unpack2(a11, f2, f3);
            float* p = hD + j0 * XROW + 2 * b0 + 2;
            st_dup2(p,            fast_tanh(f0));
            st_dup2(p + XROW,     fast_tanh(f1));
            st_dup2(p + 2 * XROW, fast_tanh(f2));
            st_dup2(p + 3 * XROW, fast_tanh(f3));
        }
        if (havex) {   // stage x for t+1 into buf^1 (read only after next top barrier)
            float* p = xD + (buf ^ 1) * XBUF + sxk * XROW + 2 * sxb;
            st_dup2(p, xn.x); st_dup2(p + XROW, xn.y);
            st_dup2(p + 2 * XROW, xn.z); st_dup2(p + 3 * XROW, xn.w);
        }
    }
    __syncthreads();

    // epilogue: out[b] = h[b] . Wout + bout
    {
        const int eb = tid >> 4;   // 16 rows
        const int g = tid & 15;
        float s = 0.0f;
#pragma unroll
        for (int j = g; j < PH; j += 16)
            s += hD[j * XROW + 2 * eb] * __ldg(&Wout[j]);
        s += __shfl_xor_sync(0xffffffffu, s, 8);
        s += __shfl_xor_sync(0xffffffffu, s, 4);
        s += __shfl_xor_sync(0xffffffffu, s, 2);
        s += __shfl_xor_sync(0xffffffffu, s, 1);
        if (g == 0) out[base + eb] = s + __ldg(&bout[0]);
    }
}

// ---------------- launcher ----------------

extern "C" void kernel_launch(void* const* d_in, const int* in_sizes, int n_in,
                              void* d_out, int out_size) {
    const float* x    = (const float*)d_in[0];
    const int*   lens = (const int*)d_in[1];
    const float* Wxh  = (const float*)d_in[2];
    const float* Whh  = (const float*)d_in[3];
    const float* bhh  = (const float*)d_in[4];
    const float* Wout = (const float*)d_in[5];
    const float* bout = (const float*)d_in[6];
    float* out = (float*)d_out;

    cudaFuncSetAttribute(rnn_kernel, cudaFuncAttributeMaxDynamicSharedMemorySize, SMEM_BYTES);

    transpose_wxh<<<dim3(2, 4, PT), dim3(32, 8)>>>(Wxh);
    transpose_whh<<<dim3(4, 4, PT), dim3(32, 8)>>>(Whh);
    rnn_kernel<<<PB / TB, NTHR, SMEM_BYTES>>>(x, lens, bhh, Wout, bout, out);
}

// round 7
// speedup vs baseline: 1.6756x; 1.6756x over previous
#include <cuda_runtime.h>
#include <cuda_bf16.h>

// Problem dims
#define PB 2048
#define PT 512
#define PI 64
#define PH 128
#define PKW 192          // I + H
#define TB 16            // batch rows per CTA
#define NTHR 256

// SMEM layout (floats)
#define WROW 128                    // w row: 128 floats, no pad (broadcast loads -> no conflicts)
#define WBUF (PKW * WROW)           // 24576 per stage
#define W_OFF 0
#define XROW 32                     // duplicated row: 16 b * 2 copies
#define X_OFF (2 * WBUF)            // 49152
#define XBUF (PI * XROW)            // 2048
#define H_OFF (X_OFF + 2 * XBUF)    // 53248
#define HBUF (PH * XROW)            // 4096
#define B_OFF (H_OFF + HBUF)        // 57344
#define I_OFF (B_OFF + 2 * PH)      // 57600
#define SMEM_FLOATS (I_OFF + 32)    // 57632
#define SMEM_BYTES (SMEM_FLOATS * 4) // 230528 B  (fits 232448 max opt-in)

typedef unsigned long long ull;

// Pre-transposed weights: Wt[t][k][j], k in [0,192): k<64 -> W_xh, k>=64 -> W_hh
__device__ __align__(16) float g_Wt[(size_t)PT * PKW * PH];

// ---------------- helpers ----------------

__device__ __forceinline__ void cp_async16(void* smem_dst, const void* gsrc) {
    unsigned saddr = (unsigned)__cvta_generic_to_shared(smem_dst);
    asm volatile("cp.async.cg.shared.global [%0], [%1], 16;\n" :: "r"(saddr), "l"(gsrc) : "memory");
}
__device__ __forceinline__ void cp_commit() {
    asm volatile("cp.async.commit_group;\n" ::: "memory");
}
__device__ __forceinline__ void cp_wait_all() {
    asm volatile("cp.async.wait_group 0;\n" ::: "memory");
}

// packed fp32x2 FMA (Blackwell FFMA2)
__device__ __forceinline__ void ffma2(ull& d, ull a, ull b) {
    asm("fma.rn.f32x2 %0, %1, %2, %0;" : "+l"(d) : "l"(a), "l"(b));
}
__device__ __forceinline__ void unpack2(ull v, float& lo, float& hi) {
    asm("mov.b64 {%0, %1}, %2;" : "=f"(lo), "=f"(hi) : "l"(v));
}
// store duplicated pair {v, v} (8B)
__device__ __forceinline__ void st_dup2(float* p, float v) {
    unsigned saddr = (unsigned)__cvta_generic_to_shared(p);
    asm volatile("st.shared.v2.f32 [%0], {%1, %1};" :: "r"(saddr), "f"(v) : "memory");
}

__device__ __forceinline__ float fast_tanh(float v) {
    v = fminf(9.0f, fmaxf(-9.0f, v));
    float e = __expf(2.0f * v);
    return __fdividef(e - 1.0f, e + 1.0f);
}

// ---------------- pre-transpose kernels ----------------
// Wt[(t*192 + k)*128 + j] = (k<64) ? Wxh[(t*128+j)*64 + k] : Whh[(t*128+j)*128 + (k-64)]

__global__ void transpose_wxh(const float* __restrict__ Wxh) {
    __shared__ float tile[32][33];
    int t = blockIdx.z;
    int k0 = blockIdx.x * 32;
    int j0 = blockIdx.y * 32;
    for (int i = threadIdx.y; i < 32; i += 8)
        tile[i][threadIdx.x] = Wxh[((size_t)t * PH + (j0 + i)) * PI + k0 + threadIdx.x];
    __syncthreads();
    for (int i = threadIdx.y; i < 32; i += 8)
        g_Wt[((size_t)t * PKW + (k0 + i)) * PH + j0 + threadIdx.x] = tile[threadIdx.x][i];
}

__global__ void transpose_whh(const float* __restrict__ Whh) {
    __shared__ float tile[32][33];
    int t = blockIdx.z;
    int k0 = blockIdx.x * 32;
    int j0 = blockIdx.y * 32;
    for (int i = threadIdx.y; i < 32; i += 8)
        tile[i][threadIdx.x] = Whh[((size_t)t * PH + (j0 + i)) * PH + k0 + threadIdx.x];
    __syncthreads();
    for (int i = threadIdx.y; i < 32; i += 8)
        g_Wt[((size_t)t * PKW + (64 + k0 + i)) * PH + j0 + threadIdx.x] = tile[threadIdx.x][i];
}

// ---------------- main RNN kernel ----------------

__device__ __forceinline__ void load_w(int t, int buf, int tid,
                                       float* wS, float* bS,
                                       const float* __restrict__ bhh) {
    const float* src = g_Wt + (size_t)t * PKW * PH;
    float* dst = wS + buf * WBUF;
    // contiguous 96 KB: 6144 chunks of 16B, 24 per thread
#pragma unroll
    for (int i = 0; i < 24; i++) {
        int c = tid + i * NTHR;
        cp_async16(dst + c * 4, src + c * 4);
    }
    if (tid < 32)
        cp_async16(bS + buf * PH + tid * 4, bhh + (size_t)t * PH + tid * 4);
}

__global__ void __launch_bounds__(NTHR)
rnn_kernel(const float* __restrict__ x, const int* __restrict__ lens,
           const float* __restrict__ bhh, const float* __restrict__ Wout,
           const float* __restrict__ bout, float* __restrict__ out) {
    extern __shared__ float sm[];
    float* wS = sm + W_OFF;
    float* xD = sm + X_OFF;   // [2][64][32]  duplicated-transposed x
    float* hD = sm + H_OFF;   // [128][32]    duplicated-transposed h
    float* bS = sm + B_OFF;
    int* iS = (int*)(sm + I_OFF);

    const int tid  = threadIdx.x;
    const int wid  = tid >> 5;
    const int lane = tid & 31;
    const int jqo  = lane & 3;        // which of warp's 4 j-quads
    const int bp   = lane >> 2;       // batch-pair 0..7
    const int j0   = wid * 16 + jqo * 4;  // thread's 4 j outputs
    const int b0   = bp * 2;
    const int base = blockIdx.x * TB;

    if (tid < TB) iS[tid] = lens[base + tid];
    for (int i = tid; i < HBUF; i += NTHR) hD[i] = 0.0f;
    __syncthreads();
    if (tid == 0) {
        int m = 0;
#pragma unroll
        for (int i = 0; i < TB; i++) m = max(m, iS[i]);
        iS[TB] = m;
    }
    __syncthreads();

    const int tmax = iS[TB];
    const int len0 = iS[b0];
    const int len1 = iS[b0 + 1];

    // x staging mapping: thread -> (row sxb, k-quad sxk); tids 0..15 coalesce over k
    const int sxb = tid >> 4;
    const int sxk = (tid & 15) * 4;
    const float* xsrc = x + ((size_t)(base + sxb) * PT) * PI + sxk;

    if (tmax > 0) {
        float4 xr = *(const float4*)xsrc;   // t = 0
        {
            float* p = xD + sxk * XROW + 2 * sxb;
            st_dup2(p, xr.x); st_dup2(p + XROW, xr.y);
            st_dup2(p + 2 * XROW, xr.z); st_dup2(p + 3 * XROW, xr.w);
        }
        load_w(0, 0, tid, wS, bS, bhh);
        cp_commit();
    }

    for (int t = 0; t < tmax; t++) {
        const int buf = t & 1;
        cp_wait_all();
        __syncthreads();   // stage t visible; prior-iter readers of buf^1 done

        if (t + 1 < tmax) load_w(t + 1, buf ^ 1, tid, wS, bS, bhh);
        cp_commit();
        const bool havex = (t + 1 < tmax);
        float4 xn;
        if (havex) xn = *(const float4*)(xsrc + (size_t)(t + 1) * PI);

        const float* wb = wS + buf * WBUF + j0;
        const float* ab = xD + buf * XBUF + bp * 4;
        const float* bb = bS + buf * PH;

        // acc[pair p][batch i]; pairs: (j0,j0+1) and (j0+2,j0+3)
        ulonglong2 bv = *(const ulonglong2*)(bb + j0);
        ull a00 = bv.x, a01 = bv.x;   // pair 0, b0 / b0+1
        ull a10 = bv.y, a11 = bv.y;   // pair 1, b0 / b0+1

        // x phase: k in [0,64)
#pragma unroll 8
        for (int k = 0; k < PI; k++) {
            ulonglong2 wv = *(const ulonglong2*)(wb + k * WROW);
            ulonglong2 av = *(const ulonglong2*)(ab + k * XROW);
            ffma2(a00, wv.x, av.x);
            ffma2(a01, wv.x, av.y);
            ffma2(a10, wv.y, av.x);
            ffma2(a11, wv.y, av.y);
        }
        // h phase: k in [0,128)
        {
            const float* wh = wb + PI * WROW;
            const float* hb = hD + bp * 4;
#pragma unroll 8
            for (int k = 0; k < PH; k++) {
                ulonglong2 wv = *(const ulonglong2*)(wh + k * WROW);
                ulonglong2 av = *(const ulonglong2*)(hb + k * XROW);
                ffma2(a00, wv.x, av.x);
                ffma2(a01, wv.x, av.y);
                ffma2(a10, wv.y, av.x);
                ffma2(a11, wv.y, av.y);
            }
        }

        __syncthreads();   // all hD reads done before writes

        if (t < len0) {
            float f0, f1, f2, f3;
            unpack2(a00, f0, f1);
            unpack2(a10, f2, f3);
            float* p = hD + j0 * XROW + 2 * b0;
            st_dup2(p,            fast_tanh(f0));
            st_dup2(p + XROW,     fast_tanh(f1));
            st_dup2(p + 2 * XROW, fast_tanh(f2));
            st_dup2(p + 3 * XROW, fast_tanh(f3));
        }
        if (t < len1) {
            float f0, f1, f2, f3;
            unpack2(a01, f0, f1);
            unpack2(a11, f2, f3);
            float* p = hD + j0 * XROW + 2 * b0 + 2;
            st_dup2(p,            fast_tanh(f0));
            st_dup2(p + XROW,     fast_tanh(f1));
            st_dup2(p + 2 * XROW, fast_tanh(f2));
            st_dup2(p + 3 * XROW, fast_tanh(f3));
        }
        if (havex) {   // stage x for t+1 into buf^1 (read only after next top barrier)
            float* p = xD + (buf ^ 1) * XBUF + sxk * XROW + 2 * sxb;
            st_dup2(p, xn.x); st_dup2(p + XROW, xn.y);
            st_dup2(p + 2 * XROW, xn.z); st_dup2(p + 3 * XROW, xn.w);
        }
    }
    __syncthreads();

    // epilogue: out[b] = h[b] . Wout + bout
    {
        const int eb = tid >> 4;   // 16 rows
        const int g = tid & 15;
        float s = 0.0f;
#pragma unroll
        for (int j = g; j < PH; j += 16)
            s += hD[j * XROW + 2 * eb] * __ldg(&Wout[j]);
        s += __shfl_xor_sync(0xffffffffu, s, 8);
        s += __shfl_xor_sync(0xffffffffu, s, 4);
        s += __shfl_xor_sync(0xffffffffu, s, 2);
        s += __shfl_xor_sync(0xffffffffu, s, 1);
        if (g == 0) out[base + eb] = s + __ldg(&bout[0]);
    }
}

// ---------------- launcher ----------------

extern "C" void kernel_launch(void* const* d_in, const int* in_sizes, int n_in,
                              void* d_out, int out_size) {
    const float* x    = (const float*)d_in[0];
    const int*   lens = (const int*)d_in[1];
    const float* Wxh  = (const float*)d_in[2];
    const float* Whh  = (const float*)d_in[3];
    const float* bhh  = (const float*)d_in[4];
    const float* Wout = (const float*)d_in[5];
    const float* bout = (const float*)d_in[6];
    float* out = (float*)d_out;

    cudaFuncSetAttribute(rnn_kernel, cudaFuncAttributeMaxDynamicSharedMemorySize, SMEM_BYTES);

    transpose_wxh<<<dim3(2, 4, PT), dim3(32, 8)>>>(Wxh);
    transpose_whh<<<dim3(4, 4, PT), dim3(32, 8)>>>(Whh);
    rnn_kernel<<<PB / TB, NTHR, SMEM_BYTES>>>(x, lens, bhh, Wout, bout, out);
}

// round 11
// speedup vs baseline: 2.6571x; 1.5858x over previous
#include <cuda_runtime.h>
#include <cuda_bf16.h>
#include <cstdint>

// Problem dims
#define PB 2048
#define PT 512
#define PI 64
#define PH 128
#define TB 32
#define NTHR 256
#define NCTA (PB / TB)

#define SCRW 132   // padded scratch row (floats)

// SMEM byte offsets
#define OSBX0 0u          // x fragments buf0: 4kblk x 4nblk x 32lane x 16B = 8192
#define OSBX1 8192u
#define OSBH  16384u      // h fragments: 8kblk x 4nblk x 32lane x 16B = 16384
#define OSCR  32768u      // fp32 h scratch: 32 x 132 floats = 16896
#define OLEN  49664u      // 32 ints
#define SMEMB 49824u

// A fragments: [t][kblk 12][half 2][mblk 8][lane 32] x 16B (uint4)
__device__ __align__(16) uint4 g_WA[(size_t)PT * 12 * 2 * 8 * 32];

// ---------------- helpers ----------------

__device__ __forceinline__ unsigned short bfb(__nv_bfloat16 h) {
    return *reinterpret_cast<unsigned short*>(&h);
}
// pack two floats to bf16x2 hi; set lo = bf16x2 of residuals
__device__ __forceinline__ uint32_t pack2(float a, float b, uint32_t& lo) {
    __nv_bfloat16 ha = __float2bfloat16(a), hb = __float2bfloat16(b);
    __nv_bfloat16 la = __float2bfloat16(a - __bfloat162float(ha));
    __nv_bfloat16 lb = __float2bfloat16(b - __bfloat162float(hb));
    lo = (uint32_t)bfb(la) | ((uint32_t)bfb(lb) << 16);
    return (uint32_t)bfb(ha) | ((uint32_t)bfb(hb) << 16);
}
// pack selecting hi (half=0) or lo (half=1)
__device__ __forceinline__ uint32_t packsel(float a, float b, int half) {
    __nv_bfloat16 ha = __float2bfloat16(a), hb = __float2bfloat16(b);
    if (half) {
        ha = __float2bfloat16(a - __bfloat162float(ha));
        hb = __float2bfloat16(b - __bfloat162float(hb));
    }
    return (uint32_t)bfb(ha) | ((uint32_t)bfb(hb) << 16);
}
__device__ __forceinline__ float fast_tanh(float v) {
    v = fminf(9.0f, fmaxf(-9.0f, v));
    float e = __expf(2.0f * v);
    return __fdividef(e - 1.0f, e + 1.0f);
}
__device__ __forceinline__ void mma16816(float* c,
                                         uint32_t a0, uint32_t a1, uint32_t a2, uint32_t a3,
                                         uint32_t b0, uint32_t b1) {
    asm volatile(
        "mma.sync.aligned.m16n8k16.row.col.f32.bf16.bf16.f32 "
        "{%0,%1,%2,%3}, {%4,%5,%6,%7}, {%8,%9}, {%0,%1,%2,%3};"
        : "+f"(c[0]), "+f"(c[1]), "+f"(c[2]), "+f"(c[3])
        : "r"(a0), "r"(a1), "r"(a2), "r"(a3), "r"(b0), "r"(b1));
}

// ---------------- prepass: weights -> A-fragment layout ----------------
// chunk (t, kblk, half, mblk, lane): g = lane>>2, t4 = lane&3
//   j0 = mblk*16+g, j1 = j0+8; k0 = kblk*16 + 2*t4; k2 = k0+8
//   chunk = { pack(W[j0][k0],W[j0][k0+1]), pack(W[j1][k0],W[j1][k0+1]),
//             pack(W[j0][k2],W[j0][k2+1]), pack(W[j1][k2],W[j1][k2+1]) }  (hi or lo per half)
// W[j][k] = k<64 ? Wxh[t][j][k] : Whh[t][j][k-64]

__global__ void prep_weights(const float* __restrict__ Wxh, const float* __restrict__ Whh) {
    const int t = blockIdx.x;
    for (int i = threadIdx.x; i < 6144; i += 256) {
        int lane = i & 31, mblk = (i >> 5) & 7, half = (i >> 8) & 1, kblk = i >> 9;
        int g = lane >> 2, t4 = lane & 3;
        int j0 = mblk * 16 + g;
        int k0 = kblk * 16 + 2 * t4;
        const float* r0;
        const float* r1;
        if (k0 < PI) {
            r0 = Wxh + ((size_t)t * PH + j0) * PI + k0;
            r1 = Wxh + ((size_t)t * PH + j0 + 8) * PI + k0;
        } else {
            r0 = Whh + ((size_t)t * PH + j0) * PH + (k0 - PI);
            r1 = Whh + ((size_t)t * PH + j0 + 8) * PH + (k0 - PI);
        }
        float2 u0 = *(const float2*)r0;
        float2 u2 = *(const float2*)(r0 + 8);
        float2 v0 = *(const float2*)r1;
        float2 v2 = *(const float2*)(r1 + 8);
        uint4 c;
        c.x = packsel(u0.x, u0.y, half);
        c.y = packsel(v0.x, v0.y, half);
        c.z = packsel(u2.x, u2.y, half);
        c.w = packsel(v2.x, v2.y, half);
        g_WA[((((size_t)t * 12 + kblk) * 2 + half) * 8 + mblk) * 32 + lane] = c;
    }
}

// ---------------- main kernel ----------------

__global__ void __launch_bounds__(NTHR, 1)
rnn_mma(const float* __restrict__ x, const int* __restrict__ lens,
        const float* __restrict__ bhh, const float* __restrict__ Wout,
        const float* __restrict__ bout, float* __restrict__ out) {
    extern __shared__ unsigned char sm[];
    float* SCR = (float*)(sm + OSCR);
    int* LEN = (int*)(sm + OLEN);

    const int tid = threadIdx.x;
    const int wid = tid >> 5;
    const int lane = tid & 31;
    const int g = lane >> 2;
    const int t4 = lane & 3;
    const int base = blockIdx.x * TB;

    if (tid < TB) LEN[tid] = lens[base + tid];
    for (int i = tid; i < TB * SCRW; i += NTHR) SCR[i] = 0.0f;
    for (int i = tid; i < 1024; i += NTHR) ((uint4*)(sm + OSBH))[i] = make_uint4(0, 0, 0, 0);
    __syncthreads();

    int tmax = 0;
#pragma unroll
    for (int i = 0; i < TB; i++) tmax = max(tmax, LEN[i]);

    // producer setup (warps 4-7): x fragment chunks
    const int wq = wid - 4;                 // 0..3 = nblk
    const float* xrow = x + (size_t)(base + ((wq < 0 ? 0 : wq) * 8 + g)) * PT * PI;

    // mma setup (warps 0-3)
    float acc[2][4][4];
    uint4 aSt[2][2][2];   // [stage][mblk][half]
    int lenr[4][2];
    if (wid < 4) {
#pragma unroll
        for (int nb = 0; nb < 4; nb++) {
            lenr[nb][0] = LEN[nb * 8 + 2 * t4];
            lenr[nb][1] = LEN[nb * 8 + 2 * t4 + 1];
        }
    }

    // prologue: x(0) fragments + A(0, kblk 0..1) prefetch
    if (tmax > 0) {
        if (wid >= 4) {
#pragma unroll
            for (int i = 0; i < 4; i++) {
                const float* p = xrow + i * 16 + 2 * t4;   // t = 0
                float2 u = *(const float2*)p;
                float2 v = *(const float2*)(p + 8);
                uint32_t l0, l1;
                uint32_t h0 = pack2(u.x, u.y, l0);
                uint32_t h1 = pack2(v.x, v.y, l1);
                *(uint4*)(sm + OSBX0 + (((uint32_t)(i * 4 + wq) * 32 + lane) * 16)) =
                    make_uint4(h0, h1, l0, l1);
            }
        } else {
#pragma unroll
            for (int s = 0; s < 2; s++) {
                const uint4* ap = g_WA + ((((size_t)0 * 12 + s) * 2) * 8 + 2 * wid) * 32 + lane;
                aSt[s][0][0] = ap[0];   aSt[s][1][0] = ap[32];
                aSt[s][0][1] = ap[256]; aSt[s][1][1] = ap[256 + 32];
            }
        }
    }
    __syncthreads();

    for (int t = 0; t < tmax; t++) {
        if (wid < 4) {
            // bias prefetch (consumed post-mma)
            float bias[2][2];
#pragma unroll
            for (int mb = 0; mb < 2; mb++)
#pragma unroll
                for (int jr = 0; jr < 2; jr++)
                    bias[mb][jr] = __ldg(bhh + (size_t)t * PH + wid * 32 + mb * 16 + g + 8 * jr);

#pragma unroll
            for (int mb = 0; mb < 2; mb++)
#pragma unroll
                for (int nb = 0; nb < 4; nb++)
#pragma unroll
                    for (int q = 0; q < 4; q++) acc[mb][nb][q] = 0.0f;

            const unsigned char* sbx = sm + ((t & 1) ? OSBX1 : OSBX0);
            const unsigned char* sbh = sm + OSBH;

            uint4 bB[2][4];
#pragma unroll
            for (int nb = 0; nb < 4; nb++)
                bB[0][nb] = *(const uint4*)(sbx + (uint32_t)(nb * 32 + lane) * 16);

#pragma unroll
            for (int kb = 0; kb < 12; kb++) {
                const int cur = kb & 1, nxt = cur ^ 1;
                // B prefetch kb+1
                if (kb < 11) {
                    const unsigned char* bp = (kb + 1 < 4)
                        ? sbx + (uint32_t)(kb + 1) * 2048
                        : sbh + (uint32_t)(kb - 3) * 2048;
#pragma unroll
                    for (int nb = 0; nb < 4; nb++)
                        bB[nxt][nb] = *(const uint4*)(bp + (uint32_t)(nb * 512 + lane * 16));
                }
                // consume A stage
                uint4 AH0 = aSt[cur][0][0], AH1 = aSt[cur][1][0];
                uint4 AL0 = aSt[cur][0][1], AL1 = aSt[cur][1][1];
                // A prefetch kb+2 (possibly next t)
                {
                    int nk = kb + 2, nt = t;
                    if (nk >= 12) { nk -= 12; nt = (t + 1 < tmax) ? t + 1 : t; }
                    const uint4* ap = g_WA + ((((size_t)nt * 12 + nk) * 2) * 8 + 2 * wid) * 32 + lane;
                    aSt[cur][0][0] = ap[0];   aSt[cur][1][0] = ap[32];
                    aSt[cur][0][1] = ap[256]; aSt[cur][1][1] = ap[256 + 32];
                }
                // term 1: Ahi x Bhi
#pragma unroll
                for (int mb = 0; mb < 2; mb++) {
                    uint4 A = mb ? AH1 : AH0;
#pragma unroll
                    for (int nb = 0; nb < 4; nb++)
                        mma16816(acc[mb][nb], A.x, A.y, A.z, A.w, bB[cur][nb].x, bB[cur][nb].y);
                }
                // term 2: Ahi x Blo
#pragma unroll
                for (int mb = 0; mb < 2; mb++) {
                    uint4 A = mb ? AH1 : AH0;
#pragma unroll
                    for (int nb = 0; nb < 4; nb++)
                        mma16816(acc[mb][nb], A.x, A.y, A.z, A.w, bB[cur][nb].z, bB[cur][nb].w);
                }
                // term 3: Alo x Bhi
#pragma unroll
                for (int mb = 0; mb < 2; mb++) {
                    uint4 A = mb ? AL1 : AL0;
#pragma unroll
                    for (int nb = 0; nb < 4; nb++)
                        mma16816(acc[mb][nb], A.x, A.y, A.z, A.w, bB[cur][nb].x, bB[cur][nb].y);
                }
            }

            // epilogue: bias + tanh + freeze-mask -> fp32 scratch
#pragma unroll
            for (int mb = 0; mb < 2; mb++) {
                const int j0 = wid * 32 + mb * 16 + g;
#pragma unroll
                for (int nb = 0; nb < 4; nb++) {
                    const int b0 = nb * 8 + 2 * t4;
                    if (t < lenr[nb][0]) {
                        SCR[b0 * SCRW + j0]     = fast_tanh(acc[mb][nb][0] + bias[mb][0]);
                        SCR[b0 * SCRW + j0 + 8] = fast_tanh(acc[mb][nb][2] + bias[mb][1]);
                    }
                    if (t < lenr[nb][1]) {
                        SCR[(b0 + 1) * SCRW + j0]     = fast_tanh(acc[mb][nb][1] + bias[mb][0]);
                        SCR[(b0 + 1) * SCRW + j0 + 8] = fast_tanh(acc[mb][nb][3] + bias[mb][1]);
                    }
                }
            }
        } else if (t + 1 < tmax) {
            // producers: x(t+1) fragments into the other buffer
            unsigned char* dst = sm + (((t + 1) & 1) ? OSBX1 : OSBX0);
#pragma unroll
            for (int i = 0; i < 4; i++) {
                const float* p = xrow + (size_t)(t + 1) * PI + i * 16 + 2 * t4;
                float2 u = *(const float2*)p;
                float2 v = *(const float2*)(p + 8);
                uint32_t l0, l1;
                uint32_t h0 = pack2(u.x, u.y, l0);
                uint32_t h1 = pack2(v.x, v.y, l1);
                *(uint4*)(dst + ((uint32_t)(i * 4 + wq) * 32 + lane) * 16) =
                    make_uint4(h0, h1, l0, l1);
            }
        }
        __syncthreads();   // scratch h(t) + x(t+1) frags visible

        // all 256 threads: rebuild h fragments from scratch (1024 chunks)
#pragma unroll
        for (int i = 0; i < 4; i++) {
            int c = tid + NTHR * i;
            int lc = c & 31, nb = (c >> 5) & 3, kb = c >> 7;   // kb in [0,8)
            int gg = lc >> 2, tt4 = lc & 3;
            int b = nb * 8 + gg;
            int jb = kb * 16 + 2 * tt4;
            float2 u = *(const float2*)&SCR[b * SCRW + jb];
            float2 v = *(const float2*)&SCR[b * SCRW + jb + 8];
            uint32_t l0, l1;
            uint32_t h0 = pack2(u.x, u.y, l0);
            uint32_t h1 = pack2(v.x, v.y, l1);
            *(uint4*)(sm + OSBH + ((uint32_t)((kb * 4 + nb) * 32 + lc) * 16)) =
                make_uint4(h0, h1, l0, l1);
        }
        __syncthreads();   // h frags ready for step t+1
    }

    // ---- final projection from fp32 scratch ----
    {
        const int b = tid >> 3;       // 32 batch rows
        const int part = tid & 7;
        float s = 0.0f;
#pragma unroll
        for (int q = 0; q < 16; q++) {
            int jj = part * 16 + q;
            s += SCR[b * SCRW + jj] * __ldg(&Wout[jj]);
        }
        s += __shfl_xor_sync(0xffffffffu, s, 4);
        s += __shfl_xor_sync(0xffffffffu, s, 2);
        s += __shfl_xor_sync(0xffffffffu, s, 1);
        if (part == 0) out[base + b] = s + __ldg(bout);
    }
}

// ---------------- launcher ----------------

extern "C" void kernel_launch(void* const* d_in, const int* in_sizes, int n_in,
                              void* d_out, int out_size) {
    const float* x    = (const float*)d_in[0];
    const int*   lens = (const int*)d_in[1];
    const float* Wxh  = (const float*)d_in[2];
    const float* Whh  = (const float*)d_in[3];
    const float* bhh  = (const float*)d_in[4];
    const float* Wout = (const float*)d_in[5];
    const float* bout = (const float*)d_in[6];
    float* out = (float*)d_out;

    cudaFuncSetAttribute(rnn_mma, cudaFuncAttributeMaxDynamicSharedMemorySize, SMEMB);

    prep_weights<<<PT, 256>>>(Wxh, Whh);
    rnn_mma<<<NCTA, NTHR, SMEMB>>>(x, lens, bhh, Wout, bout, out);
}

// round 13
// speedup vs baseline: 4.0054x; 1.5074x over previous
#include <cuda_runtime.h>
#include <cuda_bf16.h>
#include <cstdint>

// Problem dims
#define PB 2048
#define PT 512
#define PI 64
#define PH 128
#define TB 16
#define NTHR 256
#define NCTA (PB / TB)    // 128 CTAs -> 128 SMs

#define SCRW 132   // padded scratch row (floats)

// SMEM byte offsets
#define OSBX0 0u          // x fragments buf0: 4kblk x 2nblk x 32lane x 16B = 4096
#define OSBX1 4096u
#define OSBH  8192u       // h fragments: 8kblk x 2nblk x 32lane x 16B = 8192
#define OSCR  16384u      // fp32 h scratch: 16 x 132 floats = 8448
#define OLEN  24832u      // 16 ints
#define SMEMB 24960u

// A fragments: [t][kblk 12][half 2][mblk 8][lane 32] x 16B (uint4)
__device__ __align__(16) uint4 g_WA[(size_t)PT * 12 * 2 * 8 * 32];

// ---------------- helpers ----------------

__device__ __forceinline__ unsigned short bfb(__nv_bfloat16 h) {
    return *reinterpret_cast<unsigned short*>(&h);
}
// pack two floats to bf16x2 hi; set lo = bf16x2 of residuals
__device__ __forceinline__ uint32_t pack2(float a, float b, uint32_t& lo) {
    __nv_bfloat16 ha = __float2bfloat16(a), hb = __float2bfloat16(b);
    __nv_bfloat16 la = __float2bfloat16(a - __bfloat162float(ha));
    __nv_bfloat16 lb = __float2bfloat16(b - __bfloat162float(hb));
    lo = (uint32_t)bfb(la) | ((uint32_t)bfb(lb) << 16);
    return (uint32_t)bfb(ha) | ((uint32_t)bfb(hb) << 16);
}
// pack selecting hi (half=0) or lo (half=1)
__device__ __forceinline__ uint32_t packsel(float a, float b, int half) {
    __nv_bfloat16 ha = __float2bfloat16(a), hb = __float2bfloat16(b);
    if (half) {
        ha = __float2bfloat16(a - __bfloat162float(ha));
        hb = __float2bfloat16(b - __bfloat162float(hb));
    }
    return (uint32_t)bfb(ha) | ((uint32_t)bfb(hb) << 16);
}
__device__ __forceinline__ float fast_tanh(float v) {
    v = fminf(9.0f, fmaxf(-9.0f, v));
    float e = __expf(2.0f * v);
    return __fdividef(e - 1.0f, e + 1.0f);
}
__device__ __forceinline__ void mma16816(float* c,
                                         uint32_t a0, uint32_t a1, uint32_t a2, uint32_t a3,
                                         uint32_t b0, uint32_t b1) {
    asm volatile(
        "mma.sync.aligned.m16n8k16.row.col.f32.bf16.bf16.f32 "
        "{%0,%1,%2,%3}, {%4,%5,%6,%7}, {%8,%9}, {%0,%1,%2,%3};"
        : "+f"(c[0]), "+f"(c[1]), "+f"(c[2]), "+f"(c[3])
        : "r"(a0), "r"(a1), "r"(a2), "r"(a3), "r"(b0), "r"(b1));
}

// ---------------- prepass: weights -> A-fragment layout ----------------
// (unchanged from R11 — layout independent of N)

__global__ void prep_weights(const float* __restrict__ Wxh, const float* __restrict__ Whh) {
    const int t = blockIdx.x;
    for (int i = threadIdx.x; i < 6144; i += 256) {
        int lane = i & 31, mblk = (i >> 5) & 7, half = (i >> 8) & 1, kblk = i >> 9;
        int g = lane >> 2, t4 = lane & 3;
        int j0 = mblk * 16 + g;
        int k0 = kblk * 16 + 2 * t4;
        const float* r0;
        const float* r1;
        if (k0 < PI) {
            r0 = Wxh + ((size_t)t * PH + j0) * PI + k0;
            r1 = Wxh + ((size_t)t * PH + j0 + 8) * PI + k0;
        } else {
            r0 = Whh + ((size_t)t * PH + j0) * PH + (k0 - PI);
            r1 = Whh + ((size_t)t * PH + j0 + 8) * PH + (k0 - PI);
        }
        float2 u0 = *(const float2*)r0;
        float2 u2 = *(const float2*)(r0 + 8);
        float2 v0 = *(const float2*)r1;
        float2 v2 = *(const float2*)(r1 + 8);
        uint4 c;
        c.x = packsel(u0.x, u0.y, half);
        c.y = packsel(v0.x, v0.y, half);
        c.z = packsel(u2.x, u2.y, half);
        c.w = packsel(v2.x, v2.y, half);
        g_WA[((((size_t)t * 12 + kblk) * 2 + half) * 8 + mblk) * 32 + lane] = c;
    }
}

// ---------------- main kernel ----------------

__global__ void __launch_bounds__(NTHR, 1)
rnn_mma(const float* __restrict__ x, const int* __restrict__ lens,
        const float* __restrict__ bhh, const float* __restrict__ Wout,
        const float* __restrict__ bout, float* __restrict__ out) {
    extern __shared__ unsigned char sm[];
    float* SCR = (float*)(sm + OSCR);
    int* LEN = (int*)(sm + OLEN);

    const int tid = threadIdx.x;
    const int wid = tid >> 5;
    const int lane = tid & 31;
    const int g = lane >> 2;
    const int t4 = lane & 3;
    const int base = blockIdx.x * TB;

    if (tid < TB) LEN[tid] = lens[base + tid];
    for (int i = tid; i < TB * SCRW; i += NTHR) SCR[i] = 0.0f;
    for (int i = tid; i < 512; i += NTHR) ((uint4*)(sm + OSBH))[i] = make_uint4(0, 0, 0, 0);
    __syncthreads();

    int tmax = 0;
#pragma unroll
    for (int i = 0; i < TB; i++) tmax = max(tmax, LEN[i]);

    // producer setup (warps 4-5): x fragment chunks (nblk = wid-4)
    const int wq = wid - 4;                 // 0..1 = nblk for producers
    const float* xrow = x + (size_t)(base + (((wq < 0 || wq > 1) ? 0 : wq) * 8 + g)) * PT * PI;
    const bool is_prod = (wq == 0 || wq == 1);

    // mma setup (warps 0-3)
    float acc[2][2][4];
    uint4 aSt[2][2][2];   // [stage][mblk][half]
    int lenr[2][2];
    if (wid < 4) {
#pragma unroll
        for (int nb = 0; nb < 2; nb++) {
            lenr[nb][0] = LEN[nb * 8 + 2 * t4];
            lenr[nb][1] = LEN[nb * 8 + 2 * t4 + 1];
        }
    }

    // prologue: x(0) fragments + A(0, kblk 0..1) prefetch
    if (tmax > 0) {
        if (is_prod) {
#pragma unroll
            for (int i = 0; i < 4; i++) {
                const float* p = xrow + i * 16 + 2 * t4;   // t = 0
                float2 u = *(const float2*)p;
                float2 v = *(const float2*)(p + 8);
                uint32_t l0, l1;
                uint32_t h0 = pack2(u.x, u.y, l0);
                uint32_t h1 = pack2(v.x, v.y, l1);
                *(uint4*)(sm + OSBX0 + (((uint32_t)(i * 2 + wq) * 32 + lane) * 16)) =
                    make_uint4(h0, h1, l0, l1);
            }
        } else if (wid < 4) {
#pragma unroll
            for (int s = 0; s < 2; s++) {
                const uint4* ap = g_WA + ((((size_t)0 * 12 + s) * 2) * 8 + 2 * wid) * 32 + lane;
                aSt[s][0][0] = ap[0];   aSt[s][1][0] = ap[32];
                aSt[s][0][1] = ap[256]; aSt[s][1][1] = ap[256 + 32];
            }
        }
    }
    __syncthreads();

    for (int t = 0; t < tmax; t++) {
        if (wid < 4) {
            // bias prefetch (consumed post-mma)
            float bias[2][2];
#pragma unroll
            for (int mb = 0; mb < 2; mb++)
#pragma unroll
                for (int jr = 0; jr < 2; jr++)
                    bias[mb][jr] = __ldg(bhh + (size_t)t * PH + wid * 32 + mb * 16 + g + 8 * jr);

#pragma unroll
            for (int mb = 0; mb < 2; mb++)
#pragma unroll
                for (int nb = 0; nb < 2; nb++)
#pragma unroll
                    for (int q = 0; q < 4; q++) acc[mb][nb][q] = 0.0f;

            const unsigned char* sbx = sm + ((t & 1) ? OSBX1 : OSBX0);
            const unsigned char* sbh = sm + OSBH;

            uint4 bB[2][2];
#pragma unroll
            for (int nb = 0; nb < 2; nb++)
                bB[0][nb] = *(const uint4*)(sbx + (uint32_t)(nb * 32 + lane) * 16);

#pragma unroll
            for (int kb = 0; kb < 12; kb++) {
                const int cur = kb & 1, nxt = cur ^ 1;
                // B prefetch kb+1
                if (kb < 11) {
                    const unsigned char* bp = (kb + 1 < 4)
                        ? sbx + (uint32_t)(kb + 1) * 1024
                        : sbh + (uint32_t)(kb - 3) * 1024;
#pragma unroll
                    for (int nb = 0; nb < 2; nb++)
                        bB[nxt][nb] = *(const uint4*)(bp + (uint32_t)(nb * 512 + lane * 16));
                }
                // consume A stage
                uint4 AH0 = aSt[cur][0][0], AH1 = aSt[cur][1][0];
                uint4 AL0 = aSt[cur][0][1], AL1 = aSt[cur][1][1];
                // A prefetch kb+2 (possibly next t)
                {
                    int nk = kb + 2, nt = t;
                    if (nk >= 12) { nk -= 12; nt = (t + 1 < tmax) ? t + 1 : t; }
                    const uint4* ap = g_WA + ((((size_t)nt * 12 + nk) * 2) * 8 + 2 * wid) * 32 + lane;
                    aSt[cur][0][0] = ap[0];   aSt[cur][1][0] = ap[32];
                    aSt[cur][0][1] = ap[256]; aSt[cur][1][1] = ap[256 + 32];
                }
                // term 1: Ahi x Bhi
#pragma unroll
                for (int mb = 0; mb < 2; mb++) {
                    uint4 A = mb ? AH1 : AH0;
#pragma unroll
                    for (int nb = 0; nb < 2; nb++)
                        mma16816(acc[mb][nb], A.x, A.y, A.z, A.w, bB[cur][nb].x, bB[cur][nb].y);
                }
                // term 2: Ahi x Blo
#pragma unroll
                for (int mb = 0; mb < 2; mb++) {
                    uint4 A = mb ? AH1 : AH0;
#pragma unroll
                    for (int nb = 0; nb < 2; nb++)
                        mma16816(acc[mb][nb], A.x, A.y, A.z, A.w, bB[cur][nb].z, bB[cur][nb].w);
                }
                // term 3: Alo x Bhi
#pragma unroll
                for (int mb = 0; mb < 2; mb++) {
                    uint4 A = mb ? AL1 : AL0;
#pragma unroll
                    for (int nb = 0; nb < 2; nb++)
                        mma16816(acc[mb][nb], A.x, A.y, A.z, A.w, bB[cur][nb].x, bB[cur][nb].y);
                }
            }

            // epilogue: bias + tanh + freeze-mask -> fp32 scratch
#pragma unroll
            for (int mb = 0; mb < 2; mb++) {
                const int j0 = wid * 32 + mb * 16 + g;
#pragma unroll
                for (int nb = 0; nb < 2; nb++) {
                    const int b0 = nb * 8 + 2 * t4;
                    if (t < lenr[nb][0]) {
                        SCR[b0 * SCRW + j0]     = fast_tanh(acc[mb][nb][0] + bias[mb][0]);
                        SCR[b0 * SCRW + j0 + 8] = fast_tanh(acc[mb][nb][2] + bias[mb][1]);
                    }
                    if (t < lenr[nb][1]) {
                        SCR[(b0 + 1) * SCRW + j0]     = fast_tanh(acc[mb][nb][1] + bias[mb][0]);
                        SCR[(b0 + 1) * SCRW + j0 + 8] = fast_tanh(acc[mb][nb][3] + bias[mb][1]);
                    }
                }
            }
        } else if (is_prod && t + 1 < tmax) {
            // producers: x(t+1) fragments into the other buffer
            unsigned char* dst = sm + (((t + 1) & 1) ? OSBX1 : OSBX0);
#pragma unroll
            for (int i = 0; i < 4; i++) {
                const float* p = xrow + (size_t)(t + 1) * PI + i * 16 + 2 * t4;
                float2 u = *(const float2*)p;
                float2 v = *(const float2*)(p + 8);
                uint32_t l0, l1;
                uint32_t h0 = pack2(u.x, u.y, l0);
                uint32_t h1 = pack2(v.x, v.y, l1);
                *(uint4*)(dst + ((uint32_t)(i * 2 + wq) * 32 + lane) * 16) =
                    make_uint4(h0, h1, l0, l1);
            }
        }
        __syncthreads();   // scratch h(t) + x(t+1) frags visible

        // all 256 threads: rebuild h fragments from scratch (512 chunks, 2/thread)
#pragma unroll
        for (int i = 0; i < 2; i++) {
            int c = tid + NTHR * i;
            int lc = c & 31, nb = (c >> 5) & 1, kb = c >> 6;   // kb in [0,8)
            int gg = lc >> 2, tt4 = lc & 3;
            int b = nb * 8 + gg;
            int jb = kb * 16 + 2 * tt4;
            float2 u = *(const float2*)&SCR[b * SCRW + jb];
            float2 v = *(const float2*)&SCR[b * SCRW + jb + 8];
            uint32_t l0, l1;
            uint32_t h0 = pack2(u.x, u.y, l0);
            uint32_t h1 = pack2(v.x, v.y, l1);
            *(uint4*)(sm + OSBH + ((uint32_t)((kb * 2 + nb) * 32 + lc) * 16)) =
                make_uint4(h0, h1, l0, l1);
        }
        __syncthreads();   // h frags ready for step t+1
    }

    // ---- final projection from fp32 scratch ----
    if (tid < TB * 8) {
        const int b = tid >> 3;       // 16 batch rows
        const int part = tid & 7;
        float s = 0.0f;
#pragma unroll
        for (int q = 0; q < 16; q++) {
            int jj = part * 16 + q;
            s += SCR[b * SCRW + jj] * __ldg(&Wout[jj]);
        }
        s += __shfl_xor_sync(0xffffffffu, s, 4);
        s += __shfl_xor_sync(0xffffffffu, s, 2);
        s += __shfl_xor_sync(0xffffffffu, s, 1);
        if (part == 0) out[base + b] = s + __ldg(bout);
    }
}

// ---------------- launcher ----------------

extern "C" void kernel_launch(void* const* d_in, const int* in_sizes, int n_in,
                              void* d_out, int out_size) {
    const float* x    = (const float*)d_in[0];
    const int*   lens = (const int*)d_in[1];
    const float* Wxh  = (const float*)d_in[2];
    const float* Whh  = (const float*)d_in[3];
    const float* bhh  = (const float*)d_in[4];
    const float* Wout = (const float*)d_in[5];
    const float* bout = (const float*)d_in[6];
    float* out = (float*)d_out;

    cudaFuncSetAttribute(rnn_mma, cudaFuncAttributeMaxDynamicSharedMemorySize, SMEMB);

    prep_weights<<<PT, 256>>>(Wxh, Whh);
    rnn_mma<<<NCTA, NTHR, SMEMB>>>(x, lens, bhh, Wout, bout, out);
}

// round 15
// speedup vs baseline: 4.5116x; 1.1264x over previous
#include <cuda_runtime.h>
#include <cuda_bf16.h>
#include <cstdint>

// Problem dims
#define PB 2048
#define PT 512
#define PI 64
#define PH 128
#define TB 16
#define NTHR 256
#define NCTA (PB / TB)    // 128 CTAs -> 128 SMs

// SMEM byte offsets
#define OSBX0 0u          // x fragments buf0: 4kb x 2nb x 32lane x 16B = 4096
#define OSBX1 4096u
#define OSBH0 8192u       // h fragments buf0: 8kb x 2nb x 32lane x 16B = 8192
#define OSBH1 16384u
#define OLEN  24576u      // 16 ints
#define SMEMB 24704u

// A fragments: [t][kblk 12][half 2][mblk 8][lane 32] x 16B (uint4)
__device__ __align__(16) uint4 g_WA[(size_t)PT * 12 * 2 * 8 * 32];

// ---------------- helpers ----------------

__device__ __forceinline__ unsigned short bfb(__nv_bfloat16 h) {
    return *reinterpret_cast<unsigned short*>(&h);
}
__device__ __forceinline__ uint32_t pack2(float a, float b, uint32_t& lo) {
    __nv_bfloat16 ha = __float2bfloat16(a), hb = __float2bfloat16(b);
    __nv_bfloat16 la = __float2bfloat16(a - __bfloat162float(ha));
    __nv_bfloat16 lb = __float2bfloat16(b - __bfloat162float(hb));
    lo = (uint32_t)bfb(la) | ((uint32_t)bfb(lb) << 16);
    return (uint32_t)bfb(ha) | ((uint32_t)bfb(hb) << 16);
}
__device__ __forceinline__ uint32_t packsel(float a, float b, int half) {
    __nv_bfloat16 ha = __float2bfloat16(a), hb = __float2bfloat16(b);
    if (half) {
        ha = __float2bfloat16(a - __bfloat162float(ha));
        hb = __float2bfloat16(b - __bfloat162float(hb));
    }
    return (uint32_t)bfb(ha) | ((uint32_t)bfb(hb) << 16);
}
__device__ __forceinline__ float bflo(uint32_t u) {
    unsigned short s = (unsigned short)(u & 0xffff);
    __nv_bfloat16 h = *reinterpret_cast<__nv_bfloat16*>(&s);
    return __bfloat162float(h);
}
__device__ __forceinline__ float bfhi(uint32_t u) {
    unsigned short s = (unsigned short)(u >> 16);
    __nv_bfloat16 h = *reinterpret_cast<__nv_bfloat16*>(&s);
    return __bfloat162float(h);
}
__device__ __forceinline__ float fast_tanh(float v) {
    v = fminf(9.0f, fmaxf(-9.0f, v));
    float e = __expf(2.0f * v);
    return __fdividef(e - 1.0f, e + 1.0f);
}
__device__ __forceinline__ void mma16816(float* c,
                                         uint32_t a0, uint32_t a1, uint32_t a2, uint32_t a3,
                                         uint32_t b0, uint32_t b1) {
    asm volatile(
        "mma.sync.aligned.m16n8k16.row.col.f32.bf16.bf16.f32 "
        "{%0,%1,%2,%3}, {%4,%5,%6,%7}, {%8,%9}, {%0,%1,%2,%3};"
        : "+f"(c[0]), "+f"(c[1]), "+f"(c[2]), "+f"(c[3])
        : "r"(a0), "r"(a1), "r"(a2), "r"(a3), "r"(b0), "r"(b1));
}

// ---------------- prepass: weights -> A-fragment layout (unchanged) ----------------

__global__ void prep_weights(const float* __restrict__ Wxh, const float* __restrict__ Whh) {
    const int t = blockIdx.x;
    for (int i = threadIdx.x; i < 6144; i += 256) {
        int lane = i & 31, mblk = (i >> 5) & 7, half = (i >> 8) & 1, kblk = i >> 9;
        int g = lane >> 2, t4 = lane & 3;
        int j0 = mblk * 16 + g;
        int k0 = kblk * 16 + 2 * t4;
        const float* r0;
        const float* r1;
        if (k0 < PI) {
            r0 = Wxh + ((size_t)t * PH + j0) * PI + k0;
            r1 = Wxh + ((size_t)t * PH + j0 + 8) * PI + k0;
        } else {
            r0 = Whh + ((size_t)t * PH + j0) * PH + (k0 - PI);
            r1 = Whh + ((size_t)t * PH + j0 + 8) * PH + (k0 - PI);
        }
        float2 u0 = *(const float2*)r0;
        float2 u2 = *(const float2*)(r0 + 8);
        float2 v0 = *(const float2*)r1;
        float2 v2 = *(const float2*)(r1 + 8);
        uint4 c;
        c.x = packsel(u0.x, u0.y, half);
        c.y = packsel(v0.x, v0.y, half);
        c.z = packsel(u2.x, u2.y, half);
        c.w = packsel(v2.x, v2.y, half);
        g_WA[((((size_t)t * 12 + kblk) * 2 + half) * 8 + mblk) * 32 + lane] = c;
    }
}

// ---------------- main kernel: 8 MMA warps, 1 barrier/step ----------------

__global__ void __launch_bounds__(NTHR, 1)
rnn_mma(const float* __restrict__ x, const int* __restrict__ lens,
        const float* __restrict__ bhh, const float* __restrict__ Wout,
        const float* __restrict__ bout, float* __restrict__ out) {
    extern __shared__ unsigned char sm[];
    int* LEN = (int*)(sm + OLEN);

    const int tid = threadIdx.x;
    const int wid = tid >> 5;       // 0..7 = mblk
    const int lane = tid & 31;
    const int g = lane >> 2;
    const int t4 = lane & 3;
    const int base = blockIdx.x * TB;

    if (tid < TB) LEN[tid] = lens[base + tid];
    for (int i = tid; i < 512; i += NTHR) ((uint4*)(sm + OSBH0))[i] = make_uint4(0, 0, 0, 0);
    __syncthreads();

    int tmax = 0;
#pragma unroll
    for (int i = 0; i < TB; i++) tmax = max(tmax, LEN[i]);

    // this thread's x-conversion assignment: chunk c = wid*32+lane
    const int xb = (wid & 1) * 8 + g;           // batch row
    const int xk = (wid >> 1) * 16 + 2 * t4;    // k base
    const float* xrow = x + (size_t)(base + xb) * PT * PI + xk;

    const int lenB0 = LEN[g];
    const int lenB1 = LEN[8 + g];

    // x(0) fragments
    {
        const float* p = x + (size_t)(base + (((tid >> 5) & 1) * 8 + g)) * PT * PI + xk;
        float2 u = *(const float2*)p;
        float2 v = *(const float2*)(p + 8);
        uint32_t l0, l1;
        uint32_t h0 = pack2(u.x, u.y, l0);
        uint32_t h1 = pack2(v.x, v.y, l1);
        *(uint4*)(sm + OSBX0 + (uint32_t)(wid * 32 + lane) * 16) = make_uint4(h0, h1, l0, l1);
    }

    // A prefetch ring: depth 4 (slot = kb & 3)
    uint4 aSt[4][2];
    if (tmax > 0) {
#pragma unroll
        for (int s = 0; s < 4; s++) {
            const uint4* ap = g_WA + (((size_t)0 * 12 + s) * 16 + wid) * 32 + lane;
            aSt[s][0] = ap[0];
            aSt[s][1] = ap[256];
        }
    }
    __syncthreads();

    for (int t = 0; t < tmax; t++) {
        const float bias0 = __ldg(bhh + (size_t)t * PH + wid * 16 + g);
        const float bias1 = __ldg(bhh + (size_t)t * PH + wid * 16 + 8 + g);

        const bool havex = (t + 1 < tmax);
        float2 xu, xv;
        if (havex) {
            const float* p = xrow + (size_t)(t + 1) * PI;
            xu = *(const float2*)p;
            xv = *(const float2*)(p + 8);
        }

        float acc[2][4];
#pragma unroll
        for (int nb = 0; nb < 2; nb++)
#pragma unroll
            for (int q = 0; q < 4; q++) acc[nb][q] = 0.0f;

        const unsigned char* sbx = sm + ((t & 1) ? OSBX1 : OSBX0);
        const unsigned char* sbhR = sm + ((t & 1) ? OSBH1 : OSBH0);
        unsigned char* sbhW = sm + ((t & 1) ? OSBH0 : OSBH1);

        uint4 bB[2][2];
#pragma unroll
        for (int nb = 0; nb < 2; nb++)
            bB[0][nb] = *(const uint4*)(sbx + (uint32_t)(nb * 32 + lane) * 16);

#pragma unroll
        for (int kb = 0; kb < 12; kb++) {
            const int cur = kb & 1, nxt = cur ^ 1;
            // B prefetch kb+1
            if (kb < 11) {
                const unsigned char* bp = (kb + 1 < 4)
                    ? sbx + (uint32_t)(kb + 1) * 1024
                    : sbhR + (uint32_t)(kb - 3) * 1024;
#pragma unroll
                for (int nb = 0; nb < 2; nb++)
                    bB[nxt][nb] = *(const uint4*)(bp + (uint32_t)(nb * 32 + lane) * 16);
            }
            const int slot = kb & 3;
            uint4 AH = aSt[slot][0];
            uint4 AL = aSt[slot][1];
            // A prefetch kb+4 (wraps into t+1)
            {
                int nk = kb + 4, nt = t;
                if (nk >= 12) { nk -= 12; nt = havex ? t + 1 : t; }
                const uint4* ap = g_WA + (((size_t)nt * 12 + nk) * 16 + wid) * 32 + lane;
                aSt[slot][0] = ap[0];
                aSt[slot][1] = ap[256];
            }
            // term 1: Ahi x Bhi
#pragma unroll
            for (int nb = 0; nb < 2; nb++)
                mma16816(acc[nb], AH.x, AH.y, AH.z, AH.w, bB[cur][nb].x, bB[cur][nb].y);
            // term 2: Ahi x Blo
#pragma unroll
            for (int nb = 0; nb < 2; nb++)
                mma16816(acc[nb], AH.x, AH.y, AH.z, AH.w, bB[cur][nb].z, bB[cur][nb].w);
            // term 3: Alo x Bhi
#pragma unroll
            for (int nb = 0; nb < 2; nb++)
                mma16816(acc[nb], AL.x, AL.y, AL.z, AL.w, bB[cur][nb].x, bB[cur][nb].y);
        }

        // epilogue: bias + tanh, intra-warp fragment transpose via shuffles
        float tv[2][4];
#pragma unroll
        for (int nb = 0; nb < 2; nb++) {
            tv[nb][0] = fast_tanh(acc[nb][0] + bias0);
            tv[nb][1] = fast_tanh(acc[nb][1] + bias0);
            tv[nb][2] = fast_tanh(acc[nb][2] + bias1);
            tv[nb][3] = fast_tanh(acc[nb][3] + bias1);
        }
        const int lane_a = 8 * t4 + (g >> 1);
        const int lane_b = lane_a + 4;
        const bool odd = (g & 1);
#pragma unroll
        for (int nb = 0; nb < 2; nb++) {
            float e0 = __shfl_sync(0xffffffffu, tv[nb][0], lane_a);
            float e1 = __shfl_sync(0xffffffffu, tv[nb][1], lane_a);
            float e2 = __shfl_sync(0xffffffffu, tv[nb][2], lane_a);
            float e3 = __shfl_sync(0xffffffffu, tv[nb][3], lane_a);
            float f0 = __shfl_sync(0xffffffffu, tv[nb][0], lane_b);
            float f1 = __shfl_sync(0xffffffffu, tv[nb][1], lane_b);
            float f2 = __shfl_sync(0xffffffffu, tv[nb][2], lane_b);
            float f3 = __shfl_sync(0xffffffffu, tv[nb][3], lane_b);
            float va0 = odd ? e1 : e0;   // j = 2*t4
            float va2 = odd ? e3 : e2;   // j = 2*t4 + 8
            float vb0 = odd ? f1 : f0;   // j = 2*t4 + 1
            float vb2 = odd ? f3 : f2;   // j = 2*t4 + 9
            uint32_t cz, cw;
            uint32_t cx = pack2(va0, vb0, cz);
            uint32_t cy = pack2(va2, vb2, cw);
            const uint32_t off = (uint32_t)((wid * 2 + nb) * 32 + lane) * 16;
            const int lb = nb ? lenB1 : lenB0;   // chunk's batch col = nb*8+g
            if (t < lb)
                *(uint4*)(sbhW + off) = make_uint4(cx, cy, cz, cw);
            else
                *(uint4*)(sbhW + off) = *(const uint4*)(sbhR + off);
        }
        if (havex) {
            uint32_t l0, l1;
            uint32_t h0 = pack2(xu.x, xu.y, l0);
            uint32_t h1 = pack2(xv.x, xv.y, l1);
            unsigned char* dx = sm + ((t & 1) ? OSBX0 : OSBX1);
            *(uint4*)(dx + (uint32_t)(wid * 32 + lane) * 16) = make_uint4(h0, h1, l0, l1);
        }
        __syncthreads();
    }

    // ---- final projection from h fragments (hi+lo) ----
    const unsigned char* fin = sm + ((tmax & 1) ? OSBH1 : OSBH0);
    if (tid < 128) {
        const int b = tid >> 3;       // 16 batch rows
        const int part = tid & 7;     // kb2
        float s = 0.0f;
#pragma unroll
        for (int tt = 0; tt < 4; tt++) {
            uint4 ch = *(const uint4*)(fin +
                (uint32_t)((part * 2 + (b >> 3)) * 32 + (b & 7) * 4 + tt) * 16);
            int j = part * 16 + 2 * tt;
            s += (bflo(ch.x) + bflo(ch.z)) * __ldg(&Wout[j]);
            s += (bfhi(ch.x) + bfhi(ch.z)) * __ldg(&Wout[j + 1]);
            s += (bflo(ch.y) + bflo(ch.w)) * __ldg(&Wout[j + 8]);
            s += (bfhi(ch.y) + bfhi(ch.w)) * __ldg(&Wout[j + 9]);
        }
        s += __shfl_xor_sync(0xffffffffu, s, 4);
        s += __shfl_xor_sync(0xffffffffu, s, 2);
        s += __shfl_xor_sync(0xffffffffu, s, 1);
        if (part == 0) out[base + b] = s + __ldg(bout);
    }
}

// ---------------- launcher ----------------

extern "C" void kernel_launch(void* const* d_in, const int* in_sizes, int n_in,
                              void* d_out, int out_size) {
    const float* x    = (const float*)d_in[0];
    const int*   lens = (const int*)d_in[1];
    const float* Wxh  = (const float*)d_in[2];
    const float* Whh  = (const float*)d_in[3];
    const float* bhh  = (const float*)d_in[4];
    const float* Wout = (const float*)d_in[5];
    const float* bout = (const float*)d_in[6];
    float* out = (float*)d_out;

    cudaFuncSetAttribute(rnn_mma, cudaFuncAttributeMaxDynamicSharedMemorySize, SMEMB);

    prep_weights<<<PT, 256>>>(Wxh, Whh);
    rnn_mma<<<NCTA, NTHR, SMEMB>>>(x, lens, bhh, Wout, bout, out);
}